// round 1
// baseline (speedup 1.0000x reference)
#include <cuda_runtime.h>
#include <math.h>
#include <stdint.h>

#define BT    8192      // B*T tokens
#define DDIM  1024
#define WRD   128
#define KF    1152      // D + WR
#define HDIM  4096
#define NPATH 5
#define ZD    5120      // NPATH * D

// ---------------- scratch (device globals; allocation-free) ----------------
__device__ float g_abuf[BT * KF];                 // LN(cat(x, r_feat))
__device__ float g_hbuf[BT * HDIM];               // gelu(A@W1 + b1)
__device__ float g_vtp [BT * DDIM];               // vt + h@W2 + b2

// ---------------- helpers ----------------
__device__ __forceinline__ uint32_t cvt_tf32(float f) {
    uint32_t u;
    asm("cvt.rna.tf32.f32 %0, %1;" : "=r"(u) : "f"(f));
    return u;
}

__device__ __forceinline__ void mma_tf32(float* d, const uint32_t* a, const uint32_t* b) {
    asm volatile(
        "mma.sync.aligned.m16n8k8.row.col.f32.tf32.tf32.f32 "
        "{%0,%1,%2,%3}, {%4,%5,%6,%7}, {%8,%9}, {%0,%1,%2,%3};"
        : "+f"(d[0]), "+f"(d[1]), "+f"(d[2]), "+f"(d[3])
        : "r"(a[0]), "r"(a[1]), "r"(a[2]), "r"(a[3]),
          "r"(b[0]), "r"(b[1]));
}

__device__ __forceinline__ float gelu_tanh(float v) {
    float t = tanhf(0.7978845608028654f * (v + 0.044715f * v * v * v));
    return 0.5f * v * (1.0f + t);
}

// block reduce (nthreads multiple of 32, <= 1024)
__device__ __forceinline__ float block_reduce_sum(float v, float* red) {
    #pragma unroll
    for (int o = 16; o > 0; o >>= 1) v += __shfl_down_sync(0xffffffffu, v, o);
    int lane = threadIdx.x & 31, w = threadIdx.x >> 5;
    int nw = (blockDim.x + 31) >> 5;
    if (lane == 0) red[w] = v;
    __syncthreads();
    if (w == 0) {
        v = (lane < nw) ? red[lane] : 0.0f;
        #pragma unroll
        for (int o = 16; o > 0; o >>= 1) v += __shfl_down_sync(0xffffffffu, v, o);
        if (lane == 0) red[0] = v;
    }
    __syncthreads();
    float r = red[0];
    __syncthreads();
    return r;
}

// ---------------- K0: LN of cat(x, r_feat) -> g_abuf ----------------
__global__ void ln_fuse_kernel(const float* __restrict__ x,
                               const float* __restrict__ rf,
                               const float* __restrict__ g,
                               const float* __restrict__ b,
                               float* __restrict__ out) {
    int t = blockIdx.x;
    __shared__ float sv[KF];
    __shared__ float red[32];
    float lsum = 0.f, lsq = 0.f;
    for (int i = threadIdx.x; i < KF; i += blockDim.x) {
        float v = (i < DDIM) ? x[t * DDIM + i] : rf[t * WRD + (i - DDIM)];
        sv[i] = v;
        lsum += v; lsq += v * v;
    }
    float s  = block_reduce_sum(lsum, red);
    float sq = block_reduce_sum(lsq,  red);
    float mu = s * (1.0f / KF);
    float var = sq * (1.0f / KF) - mu * mu;
    float rs = rsqrtf(var + 1e-5f);
    for (int i = threadIdx.x; i < KF; i += blockDim.x) {
        out[t * KF + i] = (sv[i] - mu) * rs * g[i] + b[i];
    }
}

// ---------------- tf32 MMA GEMM: C[M,N] = A[M,K] @ B[K,N] ----------------
// EPI==0: out = gelu(C + bias)      (GEMM1 -> h)
// EPI==1: out = C + bias + resid    (GEMM2 -> vt')
template <int EPI>
__global__ __launch_bounds__(256)
void gemm_tf32_kernel(const float* __restrict__ A, const float* __restrict__ B,
                      const float* __restrict__ bias, const float* __restrict__ resid,
                      float* __restrict__ Cout, int M, int N, int K) {
    __shared__ float As[128 * 36];   // 128 rows x 32 cols, pad to 36
    __shared__ float Bs[32 * 132];   // 32  rows x 128 cols, pad to 132

    const int tid  = threadIdx.x;
    const int lane = tid & 31;
    const int warp = tid >> 5;
    const int wm = warp >> 2;        // 0..1 (64 rows)
    const int wn = warp & 3;         // 0..3 (32 cols)
    const int mb = blockIdx.y * 128;
    const int nb = blockIdx.x * 128;
    const int r = lane >> 2;         // group id
    const int c = lane & 3;          // thread in group

    float acc[4][4][4];
    #pragma unroll
    for (int mi = 0; mi < 4; mi++)
        #pragma unroll
        for (int ni = 0; ni < 4; ni++)
            #pragma unroll
            for (int j = 0; j < 4; j++) acc[mi][ni][j] = 0.0f;

    for (int kt = 0; kt < K; kt += 32) {
        // global -> shared: A tile 128x32 (8 float4 per row)
        #pragma unroll
        for (int i = 0; i < 4; i++) {
            int lin = tid + i * 256;
            int row = lin >> 3, c4 = lin & 7;
            float4 v = *reinterpret_cast<const float4*>(&A[(size_t)(mb + row) * K + kt + c4 * 4]);
            *reinterpret_cast<float4*>(&As[row * 36 + c4 * 4]) = v;
        }
        // B tile 32x128 (32 float4 per row)
        #pragma unroll
        for (int i = 0; i < 4; i++) {
            int lin = tid + i * 256;
            int row = lin >> 5, c4 = lin & 31;
            float4 v = *reinterpret_cast<const float4*>(&B[(size_t)(kt + row) * N + nb + c4 * 4]);
            *reinterpret_cast<float4*>(&Bs[row * 132 + c4 * 4]) = v;
        }
        __syncthreads();

        #pragma unroll
        for (int kk = 0; kk < 32; kk += 8) {
            uint32_t afr[4][4];
            uint32_t bfr[4][2];
            #pragma unroll
            for (int mi = 0; mi < 4; mi++) {
                int m0 = wm * 64 + mi * 16;
                afr[mi][0] = cvt_tf32(As[(m0 + r) * 36 + kk + c]);
                afr[mi][1] = cvt_tf32(As[(m0 + r + 8) * 36 + kk + c]);
                afr[mi][2] = cvt_tf32(As[(m0 + r) * 36 + kk + c + 4]);
                afr[mi][3] = cvt_tf32(As[(m0 + r + 8) * 36 + kk + c + 4]);
            }
            #pragma unroll
            for (int ni = 0; ni < 4; ni++) {
                int col = wn * 32 + ni * 8 + r;
                bfr[ni][0] = cvt_tf32(Bs[(kk + c) * 132 + col]);
                bfr[ni][1] = cvt_tf32(Bs[(kk + 4 + c) * 132 + col]);
            }
            #pragma unroll
            for (int mi = 0; mi < 4; mi++)
                #pragma unroll
                for (int ni = 0; ni < 4; ni++)
                    mma_tf32(acc[mi][ni], afr[mi], bfr[ni]);
        }
        __syncthreads();
    }

    // epilogue
    #pragma unroll
    for (int mi = 0; mi < 4; mi++) {
        int row0 = mb + wm * 64 + mi * 16 + r;
        #pragma unroll
        for (int ni = 0; ni < 4; ni++) {
            int col0 = nb + wn * 32 + ni * 8 + 2 * c;
            #pragma unroll
            for (int half = 0; half < 2; half++) {
                int row = row0 + half * 8;
                float v0 = acc[mi][ni][half * 2 + 0] + bias[col0];
                float v1 = acc[mi][ni][half * 2 + 1] + bias[col0 + 1];
                if (EPI == 0) {
                    v0 = gelu_tanh(v0);
                    v1 = gelu_tanh(v1);
                } else {
                    v0 += resid[(size_t)row * N + col0];
                    v1 += resid[(size_t)row * N + col0 + 1];
                }
                float2 o = make_float2(v0, v1);
                *reinterpret_cast<float2*>(&Cout[(size_t)row * N + col0]) = o;
            }
        }
    }
}

// ---------------- K3: path gating ----------------
__global__ __launch_bounds__(256)
void gate_kernel(const float* __restrict__ vtp, const float* __restrict__ dts,
                 const float* __restrict__ pg_g, const float* __restrict__ pg_b,
                 const float* __restrict__ gw, const float* __restrict__ gb,
                 float* __restrict__ out, float* __restrict__ gmem_out) {
    int t = blockIdx.x;
    __shared__ float z[ZD];
    __shared__ float red[32];
    __shared__ float sh5[NPATH];
    __shared__ float spi[NPATH];

    if (threadIdx.x < NPATH) sh5[threadIdx.x] = 0.0f;

    float lsum = 0.f, lsq = 0.f;
    for (int i = threadIdx.x; i < ZD; i += blockDim.x) {
        int p = i >> 10, d = i & 1023;
        float v = (p == 0) ? vtp[t * DDIM + d]
                           : dts[((size_t)(p - 1) * BT + t) * DDIM + d];
        z[i] = v;
        lsum += v; lsq += v * v;
    }
    float s  = block_reduce_sum(lsum, red);
    float sq = block_reduce_sum(lsq,  red);
    float mu = s * (1.0f / ZD);
    float rs = rsqrtf(sq * (1.0f / ZD) - mu * mu + 1e-5f);

    float accp[NPATH] = {0.f, 0.f, 0.f, 0.f, 0.f};
    for (int i = threadIdx.x; i < ZD; i += blockDim.x) {
        float zn = (z[i] - mu) * rs * pg_g[i] + pg_b[i];
        #pragma unroll
        for (int p = 0; p < NPATH; p++) accp[p] += zn * gw[i * NPATH + p];
    }
    #pragma unroll
    for (int p = 0; p < NPATH; p++) {
        float v = accp[p];
        #pragma unroll
        for (int o = 16; o > 0; o >>= 1) v += __shfl_down_sync(0xffffffffu, v, o);
        if ((threadIdx.x & 31) == 0) atomicAdd(&sh5[p], v);
    }
    __syncthreads();

    if (threadIdx.x == 0) {
        float lg[NPATH];
        float mx = -1e30f;
        #pragma unroll
        for (int p = 0; p < NPATH; p++) { lg[p] = sh5[p] + gb[p]; mx = fmaxf(mx, lg[p]); }
        float ssum = 0.f;
        #pragma unroll
        for (int p = 0; p < NPATH; p++) { lg[p] = expf(lg[p] - mx); ssum += lg[p]; }
        float inv = 1.0f / ssum;
        #pragma unroll
        for (int p = 0; p < NPATH; p++) spi[p] = lg[p] * inv;
        gmem_out[t] = spi[1] + spi[2] + spi[3] + spi[4];
    }
    __syncthreads();

    for (int d = threadIdx.x; d < DDIM; d += blockDim.x) {
        float o = 0.f;
        #pragma unroll
        for (int p = 0; p < NPATH; p++) o += spi[p] * z[p * DDIM + d];
        out[t * DDIM + d] = o;
    }
}

// ---------------- launch ----------------
extern "C" void kernel_launch(void* const* d_in, const int* in_sizes, int n_in,
                              void* d_out, int out_size) {
    const float* x        = (const float*)d_in[0];
    const float* vt       = (const float*)d_in[1];
    const float* dts      = (const float*)d_in[2];
    const float* r_feat   = (const float*)d_in[3];
    const float* fln_g    = (const float*)d_in[4];
    const float* fln_b    = (const float*)d_in[5];
    const float* w1       = (const float*)d_in[6];
    const float* b1       = (const float*)d_in[7];
    const float* w2       = (const float*)d_in[8];
    const float* b2       = (const float*)d_in[9];
    const float* pg_g     = (const float*)d_in[10];
    const float* pg_b     = (const float*)d_in[11];
    const float* gw       = (const float*)d_in[12];
    const float* gb       = (const float*)d_in[13];

    float* out  = (float*)d_out;                  // [BT, D]
    float* gmem = out + (size_t)BT * DDIM;        // [BT]

    float* abuf; cudaGetSymbolAddress((void**)&abuf, g_abuf);
    float* hbuf; cudaGetSymbolAddress((void**)&hbuf, g_hbuf);
    float* vtp;  cudaGetSymbolAddress((void**)&vtp,  g_vtp);

    // K0: LN(cat(x, r_feat))
    ln_fuse_kernel<<<BT, 128>>>(x, r_feat, fln_g, fln_b, abuf);

    // K1: h = gelu(A @ W1 + b1)   [8192x1152]x[1152x4096]
    {
        dim3 grid(HDIM / 128, BT / 128);
        gemm_tf32_kernel<0><<<grid, 256>>>(abuf, w1, b1, nullptr, hbuf, BT, HDIM, KF);
    }
    // K2: vt' = h @ W2 + b2 + vt  [8192x4096]x[4096x1024]
    {
        dim3 grid(DDIM / 128, BT / 128);
        gemm_tf32_kernel<1><<<grid, 256>>>(hbuf, w2, b2, vt, vtp, BT, DDIM, HDIM);
    }
    // K3: gating + mix
    gate_kernel<<<BT, 256>>>(vtp, dts, pg_g, pg_b, gw, gb, out, gmem);
}

// round 3
// speedup vs baseline: 1.1393x; 1.1393x over previous
#include <cuda_runtime.h>
#include <math.h>
#include <stdint.h>

#define BT    8192      // B*T tokens
#define DDIM  1024
#define WRD   128
#define KF    1152      // D + WR
#define HDIM  4096
#define NPATH 5
#define ZD    5120      // NPATH * D

// ---------------- scratch (device globals; allocation-free) ----------------
__device__ float g_abuf[BT * KF];                 // LN(cat(x, r_feat)), tf32-rounded
__device__ float g_hbuf[BT * HDIM];               // gelu(A@W1 + b1), tf32-rounded
__device__ float g_vtp [BT * DDIM];               // vt + h@W2 + b2 (fp32)
__device__ float g_w1r [KF * HDIM];               // w1 tf32-rounded [K,N]
__device__ float g_w2r [HDIM * DDIM];             // w2 tf32-rounded [K,N]

// ---------------- helpers ----------------
__device__ __forceinline__ uint32_t cvt_tf32(float f) {
    uint32_t u;
    asm("cvt.rna.tf32.f32 %0, %1;" : "=r"(u) : "f"(f));
    return u;
}
__device__ __forceinline__ float gelu_tanh(float v) {
    float t = tanhf(0.7978845608028654f * (v + 0.044715f * v * v * v));
    return 0.5f * v * (1.0f + t);
}
__device__ __forceinline__ uint32_t smem_u32(const void* p) {
    uint32_t a;
    asm("{ .reg .u64 t; cvta.to.shared.u64 t, %1; cvt.u32.u64 %0, t; }" : "=r"(a) : "l"(p));
    return a;
}
__device__ __forceinline__ void mma_tf32(float* d, const uint32_t* a, const uint32_t* b) {
    asm volatile(
        "mma.sync.aligned.m16n8k8.row.col.f32.tf32.tf32.f32 "
        "{%0,%1,%2,%3}, {%4,%5,%6,%7}, {%8,%9}, {%0,%1,%2,%3};"
        : "+f"(d[0]), "+f"(d[1]), "+f"(d[2]), "+f"(d[3])
        : "r"(a[0]), "r"(a[1]), "r"(a[2]), "r"(a[3]),
          "r"(b[0]), "r"(b[1]));
}
__device__ __forceinline__ void cp16(uint32_t dst, const void* src) {
    asm volatile("cp.async.cg.shared.global [%0], [%1], 16;" :: "r"(dst), "l"(src));
}
__device__ __forceinline__ void cp_commit() {
    asm volatile("cp.async.commit_group;" ::: "memory");
}
template <int N>
__device__ __forceinline__ void cp_wait() {
    asm volatile("cp.async.wait_group %0;" :: "n"(N) : "memory");
}
__device__ __forceinline__ float block_reduce_sum(float v, float* red) {
    #pragma unroll
    for (int o = 16; o > 0; o >>= 1) v += __shfl_down_sync(0xffffffffu, v, o);
    int lane = threadIdx.x & 31, w = threadIdx.x >> 5;
    int nw = (blockDim.x + 31) >> 5;
    if (lane == 0) red[w] = v;
    __syncthreads();
    if (w == 0) {
        v = (lane < nw) ? red[lane] : 0.0f;
        #pragma unroll
        for (int o = 16; o > 0; o >>= 1) v += __shfl_down_sync(0xffffffffu, v, o);
        if (lane == 0) red[0] = v;
    }
    __syncthreads();
    float r = red[0];
    __syncthreads();
    return r;
}

// ---------------- K-1: elementwise tf32 round ----------------
__global__ __launch_bounds__(256)
void round_tf32_kernel(const float* __restrict__ in, float* __restrict__ out, int n4) {
    int i = blockIdx.x * 256 + threadIdx.x;
    if (i >= n4) return;
    float4 v = ((const float4*)in)[i];
    float4 o;
    o.x = __uint_as_float(cvt_tf32(v.x));
    o.y = __uint_as_float(cvt_tf32(v.y));
    o.z = __uint_as_float(cvt_tf32(v.z));
    o.w = __uint_as_float(cvt_tf32(v.w));
    ((float4*)out)[i] = o;
}

// ---------------- K0: LN of cat(x, r_feat) -> g_abuf (tf32-rounded) ----------------
__global__ __launch_bounds__(128)
void ln_fuse_kernel(const float* __restrict__ x, const float* __restrict__ rf,
                    const float* __restrict__ g, const float* __restrict__ b,
                    float* __restrict__ out) {
    int t = blockIdx.x;
    __shared__ float4 sv4[KF / 4];
    __shared__ float red[32];
    const float4* x4  = (const float4*)x;
    const float4* rf4 = (const float4*)rf;
    float lsum = 0.f, lsq = 0.f;
    #pragma unroll
    for (int i4 = threadIdx.x; i4 < KF / 4; i4 += 128) {
        float4 v = (i4 < DDIM / 4) ? x4[(size_t)t * (DDIM / 4) + i4]
                                   : rf4[(size_t)t * (WRD / 4) + (i4 - DDIM / 4)];
        sv4[i4] = v;
        lsum += v.x + v.y + v.z + v.w;
        lsq  += v.x * v.x + v.y * v.y + v.z * v.z + v.w * v.w;
    }
    float s  = block_reduce_sum(lsum, red);
    float sq = block_reduce_sum(lsq,  red);
    float mu = s * (1.0f / KF);
    float rs = rsqrtf(sq * (1.0f / KF) - mu * mu + 1e-5f);
    const float4* g4 = (const float4*)g;
    const float4* b4 = (const float4*)b;
    float4* o4 = (float4*)out;
    #pragma unroll
    for (int i4 = threadIdx.x; i4 < KF / 4; i4 += 128) {
        float4 v = sv4[i4], gg = g4[i4], bb = b4[i4], o;
        o.x = __uint_as_float(cvt_tf32((v.x - mu) * rs * gg.x + bb.x));
        o.y = __uint_as_float(cvt_tf32((v.y - mu) * rs * gg.y + bb.y));
        o.z = __uint_as_float(cvt_tf32((v.z - mu) * rs * gg.z + bb.z));
        o.w = __uint_as_float(cvt_tf32((v.w - mu) * rs * gg.w + bb.w));
        o4[(size_t)t * (KF / 4) + i4] = o;
    }
}

// ---------------- tf32 mma.sync GEMM, cp.async double-buffered ----------------
// C[M,N] = A[M,K] @ B[K,N], both operands pre-rounded to tf32.
// CTA tile 128(M) x 256(N), BK=32. 8 warps as 2(M) x 4(N): warp tile 64x64.
#define AS_STRIDE 36              // floats per A smem row (conflict-free: r*4+c)
#define BS_STRIDE 264             // floats per B smem row (conflict-free: c*8+r)
#define A_TILE_F  (128 * AS_STRIDE)
#define B_TILE_F  (32 * BS_STRIDE)
#define GEMM_SMEM ((2 * A_TILE_F + 2 * B_TILE_F) * 4)

__device__ __forceinline__ void load_a_tile(const float* __restrict__ A, int mb, int K,
                                            int kt, uint32_t sm) {
    int tid = threadIdx.x;
    #pragma unroll
    for (int i = 0; i < 4; i++) {
        int lin = tid + i * 256;
        int row = lin >> 3, c4 = lin & 7;
        cp16(sm + (uint32_t)(row * AS_STRIDE + c4 * 4) * 4,
             &A[(size_t)(mb + row) * K + kt + c4 * 4]);
    }
}
__device__ __forceinline__ void load_b_tile(const float* __restrict__ B, int nb, int N,
                                            int kt, uint32_t sm) {
    int tid = threadIdx.x;
    #pragma unroll
    for (int i = 0; i < 8; i++) {
        int lin = tid + i * 256;
        int row = lin >> 6, c4 = lin & 63;
        cp16(sm + (uint32_t)(row * BS_STRIDE + c4 * 4) * 4,
             &B[(size_t)(kt + row) * N + nb + c4 * 4]);
    }
}

template <int EPI>
__global__ __launch_bounds__(256, 1)
void gemm_tf32_kernel(const float* __restrict__ A, const float* __restrict__ B,
                      const float* __restrict__ bias, const float* __restrict__ resid,
                      float* __restrict__ Cout, int M, int N, int K) {
    extern __shared__ float smem[];
    float* As[2] = { smem,                     smem + A_TILE_F };
    float* Bs[2] = { smem + 2 * A_TILE_F,      smem + 2 * A_TILE_F + B_TILE_F };
    uint32_t As_u[2] = { smem_u32(As[0]), smem_u32(As[1]) };
    uint32_t Bs_u[2] = { smem_u32(Bs[0]), smem_u32(Bs[1]) };

    const int tid  = threadIdx.x;
    const int lane = tid & 31;
    const int warp = tid >> 5;
    const int wm = warp >> 2;        // 0..1 -> 64 M-rows each
    const int wn = warp & 3;         // 0..3 -> 64 N-cols each
    const int mb = blockIdx.y * 128;
    const int nb = blockIdx.x * 256;
    const int r = lane >> 2;
    const int c = lane & 3;

    float acc[4][8][4];
    #pragma unroll
    for (int mi = 0; mi < 4; mi++)
        #pragma unroll
        for (int ni = 0; ni < 8; ni++)
            #pragma unroll
            for (int j = 0; j < 4; j++) acc[mi][ni][j] = 0.0f;

    const int S = K >> 5;

    load_a_tile(A, mb, K, 0, As_u[0]);
    load_b_tile(B, nb, N, 0, Bs_u[0]);
    cp_commit();

    for (int s = 0; s < S; s++) {
        int p = s & 1;
        if (s + 1 < S) {
            int q = p ^ 1;
            load_a_tile(A, mb, K, (s + 1) << 5, As_u[q]);
            load_b_tile(B, nb, N, (s + 1) << 5, Bs_u[q]);
            cp_commit();
            cp_wait<1>();
        } else {
            cp_wait<0>();
        }
        __syncthreads();

        const uint32_t* Asp = (const uint32_t*)As[p];
        const uint32_t* Bsp = (const uint32_t*)Bs[p];
        #pragma unroll
        for (int kk = 0; kk < 32; kk += 8) {
            uint32_t afr[4][4];
            uint32_t bfr[8][2];
            #pragma unroll
            for (int mi = 0; mi < 4; mi++) {
                int m0 = wm * 64 + mi * 16;
                afr[mi][0] = Asp[(m0 + r) * AS_STRIDE + kk + c];
                afr[mi][1] = Asp[(m0 + r + 8) * AS_STRIDE + kk + c];
                afr[mi][2] = Asp[(m0 + r) * AS_STRIDE + kk + c + 4];
                afr[mi][3] = Asp[(m0 + r + 8) * AS_STRIDE + kk + c + 4];
            }
            #pragma unroll
            for (int ni = 0; ni < 8; ni++) {
                int col = wn * 64 + ni * 8 + r;
                bfr[ni][0] = Bsp[(kk + c) * BS_STRIDE + col];
                bfr[ni][1] = Bsp[(kk + 4 + c) * BS_STRIDE + col];
            }
            #pragma unroll
            for (int mi = 0; mi < 4; mi++)
                #pragma unroll
                for (int ni = 0; ni < 8; ni++)
                    mma_tf32(acc[mi][ni], afr[mi], bfr[ni]);
        }
        __syncthreads();
    }

    // epilogue
    #pragma unroll
    for (int mi = 0; mi < 4; mi++) {
        int row0 = mb + wm * 64 + mi * 16 + r;
        #pragma unroll
        for (int ni = 0; ni < 8; ni++) {
            int col0 = nb + wn * 64 + ni * 8 + 2 * c;
            #pragma unroll
            for (int half = 0; half < 2; half++) {
                int row = row0 + half * 8;
                float v0 = acc[mi][ni][half * 2 + 0] + bias[col0];
                float v1 = acc[mi][ni][half * 2 + 1] + bias[col0 + 1];
                float2 o;
                if (EPI == 0) {
                    o.x = __uint_as_float(cvt_tf32(gelu_tanh(v0)));
                    o.y = __uint_as_float(cvt_tf32(gelu_tanh(v1)));
                } else {
                    float2 rv = *reinterpret_cast<const float2*>(&resid[(size_t)row * N + col0]);
                    o.x = v0 + rv.x;
                    o.y = v1 + rv.y;
                }
                *reinterpret_cast<float2*>(&Cout[(size_t)row * N + col0]) = o;
            }
        }
    }
}

// ---------------- K3: path gating ----------------
__global__ __launch_bounds__(256)
void gate_kernel(const float* __restrict__ vtp, const float* __restrict__ dts,
                 const float* __restrict__ pg_g, const float* __restrict__ pg_b,
                 const float* __restrict__ gw, const float* __restrict__ gb,
                 float* __restrict__ out, float* __restrict__ gmem_out) {
    int t = blockIdx.x;
    __shared__ float4 z4[ZD / 4];
    __shared__ float red[32];
    __shared__ float sh5[NPATH];
    __shared__ float spi[NPATH];

    if (threadIdx.x < NPATH) sh5[threadIdx.x] = 0.0f;

    const float4* vtp4 = (const float4*)vtp;
    const float4* dts4 = (const float4*)dts;
    float lsum = 0.f, lsq = 0.f;
    #pragma unroll
    for (int i4 = threadIdx.x; i4 < ZD / 4; i4 += 256) {
        int p = i4 >> 8, d4 = i4 & 255;
        float4 v = (p == 0) ? vtp4[(size_t)t * 256 + d4]
                            : dts4[((size_t)(p - 1) * BT + t) * 256 + d4];
        z4[i4] = v;
        lsum += v.x + v.y + v.z + v.w;
        lsq  += v.x * v.x + v.y * v.y + v.z * v.z + v.w * v.w;
    }
    float s  = block_reduce_sum(lsum, red);
    float sq = block_reduce_sum(lsq,  red);
    float mu = s * (1.0f / ZD);
    float rs = rsqrtf(sq * (1.0f / ZD) - mu * mu + 1e-5f);

    const float4* g4 = (const float4*)pg_g;
    const float4* b4 = (const float4*)pg_b;
    const float4* gw4 = (const float4*)gw;
    float accp[NPATH] = {0.f, 0.f, 0.f, 0.f, 0.f};
    #pragma unroll
    for (int i4 = threadIdx.x; i4 < ZD / 4; i4 += 256) {
        float4 zv = z4[i4], gg = g4[i4], bb = b4[i4];
        float zn[4];
        zn[0] = (zv.x - mu) * rs * gg.x + bb.x;
        zn[1] = (zv.y - mu) * rs * gg.y + bb.y;
        zn[2] = (zv.z - mu) * rs * gg.z + bb.z;
        zn[3] = (zv.w - mu) * rs * gg.w + bb.w;
        float gwf[20];
        #pragma unroll
        for (int q = 0; q < 5; q++)
            *reinterpret_cast<float4*>(&gwf[q * 4]) = gw4[(size_t)i4 * 5 + q];
        #pragma unroll
        for (int e = 0; e < 4; e++)
            #pragma unroll
            for (int p = 0; p < NPATH; p++)
                accp[p] += zn[e] * gwf[e * 5 + p];
    }
    #pragma unroll
    for (int p = 0; p < NPATH; p++) {
        float v = accp[p];
        #pragma unroll
        for (int o = 16; o > 0; o >>= 1) v += __shfl_down_sync(0xffffffffu, v, o);
        if ((threadIdx.x & 31) == 0) atomicAdd(&sh5[p], v);
    }
    __syncthreads();

    if (threadIdx.x == 0) {
        float lg[NPATH];
        float mx = -1e30f;
        #pragma unroll
        for (int p = 0; p < NPATH; p++) { lg[p] = sh5[p] + gb[p]; mx = fmaxf(mx, lg[p]); }
        float ssum = 0.f;
        #pragma unroll
        for (int p = 0; p < NPATH; p++) { lg[p] = expf(lg[p] - mx); ssum += lg[p]; }
        float inv = 1.0f / ssum;
        #pragma unroll
        for (int p = 0; p < NPATH; p++) spi[p] = lg[p] * inv;
        gmem_out[t] = spi[1] + spi[2] + spi[3] + spi[4];
    }
    __syncthreads();

    float4* out4 = (float4*)out;
    #pragma unroll
    for (int d4 = threadIdx.x; d4 < DDIM / 4; d4 += 256) {
        float4 o = make_float4(0.f, 0.f, 0.f, 0.f);
        #pragma unroll
        for (int p = 0; p < NPATH; p++) {
            float4 zp = z4[p * (DDIM / 4) + d4];
            o.x += spi[p] * zp.x; o.y += spi[p] * zp.y;
            o.z += spi[p] * zp.z; o.w += spi[p] * zp.w;
        }
        out4[(size_t)t * (DDIM / 4) + d4] = o;
    }
}

// ---------------- launch ----------------
extern "C" void kernel_launch(void* const* d_in, const int* in_sizes, int n_in,
                              void* d_out, int out_size) {
    const float* x        = (const float*)d_in[0];
    const float* vt       = (const float*)d_in[1];
    const float* dts      = (const float*)d_in[2];
    const float* r_feat   = (const float*)d_in[3];
    const float* fln_g    = (const float*)d_in[4];
    const float* fln_b    = (const float*)d_in[5];
    const float* w1       = (const float*)d_in[6];
    const float* b1       = (const float*)d_in[7];
    const float* w2       = (const float*)d_in[8];
    const float* b2       = (const float*)d_in[9];
    const float* pg_g     = (const float*)d_in[10];
    const float* pg_b     = (const float*)d_in[11];
    const float* gw       = (const float*)d_in[12];
    const float* gb       = (const float*)d_in[13];

    float* out  = (float*)d_out;                  // [BT, D]
    float* gmem = out + (size_t)BT * DDIM;        // [BT]

    float* abuf; cudaGetSymbolAddress((void**)&abuf, g_abuf);
    float* hbuf; cudaGetSymbolAddress((void**)&hbuf, g_hbuf);
    float* vtp;  cudaGetSymbolAddress((void**)&vtp,  g_vtp);
    float* w1r;  cudaGetSymbolAddress((void**)&w1r,  g_w1r);
    float* w2r;  cudaGetSymbolAddress((void**)&w2r,  g_w2r);

    cudaFuncSetAttribute(gemm_tf32_kernel<0>, cudaFuncAttributeMaxDynamicSharedMemorySize, GEMM_SMEM);
    cudaFuncSetAttribute(gemm_tf32_kernel<1>, cudaFuncAttributeMaxDynamicSharedMemorySize, GEMM_SMEM);

    // weight rounding (tf32, elementwise)
    {
        int n1 = KF * HDIM / 4;
        round_tf32_kernel<<<(n1 + 255) / 256, 256>>>(w1, w1r, n1);
        int n2 = HDIM * DDIM / 4;
        round_tf32_kernel<<<(n2 + 255) / 256, 256>>>(w2, w2r, n2);
    }

    // K0: LN(cat(x, r_feat)) -> abuf (tf32)
    ln_fuse_kernel<<<BT, 128>>>(x, r_feat, fln_g, fln_b, abuf);

    // K1: h = cvt_tf32(gelu(A @ W1 + b1))  [8192x1152]x[1152x4096]
    {
        dim3 grid(HDIM / 256, BT / 128);
        gemm_tf32_kernel<0><<<grid, 256, GEMM_SMEM>>>(abuf, w1r, b1, nullptr, hbuf, BT, HDIM, KF);
    }
    // K2: vt' = h @ W2 + b2 + vt  [8192x4096]x[4096x1024]
    {
        dim3 grid(DDIM / 256, BT / 128);
        gemm_tf32_kernel<1><<<grid, 256, GEMM_SMEM>>>(hbuf, w2r, b2, vt, vtp, BT, DDIM, HDIM);
    }
    // K3: gating + mix
    gate_kernel<<<BT, 256>>>(vtp, dts, pg_g, pg_b, gw, gb, out, gmem);
}

// round 4
// speedup vs baseline: 1.9507x; 1.7122x over previous
#include <cuda_runtime.h>
#include <cuda_fp16.h>
#include <math.h>
#include <stdint.h>

#define BT    8192      // B*T tokens
#define DDIM  1024
#define WRD   128
#define KF    1152      // D + WR
#define HDIM  4096
#define NPATH 5
#define ZD    5120      // NPATH * D

// ---------------- scratch (device globals; allocation-free) ----------------
__device__ __half g_abuf[BT * KF];                // LN(cat(x, r_feat)), fp16
__device__ __half g_hbuf[BT * HDIM];              // gelu(A@W1 + b1), fp16
__device__ float  g_vtp [BT * DDIM];              // vt + h@W2 + b2 (fp32)
__device__ __half g_w1t [HDIM * KF];              // w1^T [N,K] fp16
__device__ __half g_w2t [DDIM * HDIM];            // w2^T [N,K] fp16

// ---------------- helpers ----------------
__device__ __forceinline__ float gelu_tanh(float v) {
    float t = tanhf(0.7978845608028654f * (v + 0.044715f * v * v * v));
    return 0.5f * v * (1.0f + t);
}
__device__ __forceinline__ uint32_t smem_u32(const void* p) {
    uint32_t a;
    asm("{ .reg .u64 t; cvta.to.shared.u64 t, %1; cvt.u32.u64 %0, t; }" : "=r"(a) : "l"(p));
    return a;
}
__device__ __forceinline__ void mma_f16(float* d, const uint32_t* a, const uint32_t* b) {
    asm volatile(
        "mma.sync.aligned.m16n8k16.row.col.f32.f16.f16.f32 "
        "{%0,%1,%2,%3}, {%4,%5,%6,%7}, {%8,%9}, {%0,%1,%2,%3};"
        : "+f"(d[0]), "+f"(d[1]), "+f"(d[2]), "+f"(d[3])
        : "r"(a[0]), "r"(a[1]), "r"(a[2]), "r"(a[3]),
          "r"(b[0]), "r"(b[1]));
}
__device__ __forceinline__ void cp16(uint32_t dst, const void* src) {
    asm volatile("cp.async.cg.shared.global [%0], [%1], 16;" :: "r"(dst), "l"(src));
}
__device__ __forceinline__ void cp_commit() {
    asm volatile("cp.async.commit_group;" ::: "memory");
}
template <int N>
__device__ __forceinline__ void cp_wait() {
    asm volatile("cp.async.wait_group %0;" :: "n"(N) : "memory");
}
__device__ __forceinline__ float block_reduce_sum(float v, float* red) {
    #pragma unroll
    for (int o = 16; o > 0; o >>= 1) v += __shfl_down_sync(0xffffffffu, v, o);
    int lane = threadIdx.x & 31, w = threadIdx.x >> 5;
    int nw = (blockDim.x + 31) >> 5;
    if (lane == 0) red[w] = v;
    __syncthreads();
    if (w == 0) {
        v = (lane < nw) ? red[lane] : 0.0f;
        #pragma unroll
        for (int o = 16; o > 0; o >>= 1) v += __shfl_down_sync(0xffffffffu, v, o);
        if (lane == 0) red[0] = v;
    }
    __syncthreads();
    float r = red[0];
    __syncthreads();
    return r;
}

// ---------------- K-1: transpose + fp16 (w [R,C] -> wt [C,R]) ----------------
__global__ void transpose_h_kernel(const float* __restrict__ in, __half* __restrict__ out,
                                   int R, int C) {
    __shared__ float tile[32][33];
    int bx = blockIdx.x * 32;   // C
    int by = blockIdx.y * 32;   // R
    int x = bx + threadIdx.x;
    #pragma unroll
    for (int j = threadIdx.y; j < 32; j += 8)
        tile[j][threadIdx.x] = in[(size_t)(by + j) * C + x];
    __syncthreads();
    int ox = by + threadIdx.x;
    #pragma unroll
    for (int j = threadIdx.y; j < 32; j += 8)
        out[(size_t)(bx + j) * R + ox] = __float2half_rn(tile[threadIdx.x][j]);
}

// ---------------- K0: LN of cat(x, r_feat) -> g_abuf (fp16) ----------------
__global__ __launch_bounds__(128)
void ln_fuse_kernel(const float* __restrict__ x, const float* __restrict__ rf,
                    const float* __restrict__ g, const float* __restrict__ b,
                    __half* __restrict__ out) {
    int t = blockIdx.x;
    __shared__ float4 sv4[KF / 4];
    __shared__ float red[32];
    const float4* x4  = (const float4*)x;
    const float4* rf4 = (const float4*)rf;
    float lsum = 0.f, lsq = 0.f;
    #pragma unroll
    for (int i4 = threadIdx.x; i4 < KF / 4; i4 += 128) {
        float4 v = (i4 < DDIM / 4) ? x4[(size_t)t * (DDIM / 4) + i4]
                                   : rf4[(size_t)t * (WRD / 4) + (i4 - DDIM / 4)];
        sv4[i4] = v;
        lsum += v.x + v.y + v.z + v.w;
        lsq  += v.x * v.x + v.y * v.y + v.z * v.z + v.w * v.w;
    }
    float s  = block_reduce_sum(lsum, red);
    float sq = block_reduce_sum(lsq,  red);
    float mu = s * (1.0f / KF);
    float rs = rsqrtf(sq * (1.0f / KF) - mu * mu + 1e-5f);
    const float4* g4 = (const float4*)g;
    const float4* b4 = (const float4*)b;
    uint2* o4 = (uint2*)out;
    #pragma unroll
    for (int i4 = threadIdx.x; i4 < KF / 4; i4 += 128) {
        float4 v = sv4[i4], gg = g4[i4], bb = b4[i4];
        __half2 h01 = __floats2half2_rn((v.x - mu) * rs * gg.x + bb.x,
                                        (v.y - mu) * rs * gg.y + bb.y);
        __half2 h23 = __floats2half2_rn((v.z - mu) * rs * gg.z + bb.z,
                                        (v.w - mu) * rs * gg.w + bb.w);
        uint2 o;
        o.x = *reinterpret_cast<uint32_t*>(&h01);
        o.y = *reinterpret_cast<uint32_t*>(&h23);
        o4[(size_t)t * (KF / 4) + i4] = o;
    }
}

// ---------------- fp16 mma.sync GEMM, 3-stage cp.async ----------------
// C[M,N] = A[M,K] @ Bt[N,K]^T, fp16 operands, fp32 accum.
// CTA tile 128(M) x 128(N), BK=32. 8 warps as 2(M) x 4(N): warp tile 64x32.
#define TS_H   40                 // halfs per smem tile row (20 words; conflict-free)
#define TILE_H (128 * TS_H)       // halfs per tile
#define TILE_B (TILE_H * 2)       // 10240 bytes
#define NSTAGE 3
#define GEMM_SMEM (NSTAGE * 2 * TILE_B)

// load 128 rows x 32 halfs from g[(row0+row)*K + kt ...]
__device__ __forceinline__ void load_tile_h(const __half* __restrict__ g, int row0, int K,
                                            int kt, uint32_t sm) {
    int tid = threadIdx.x;
    #pragma unroll
    for (int i = 0; i < 2; i++) {
        int lin = tid + i * 256;
        int row = lin >> 2, c8 = lin & 3;
        cp16(sm + (uint32_t)(row * TS_H + c8 * 8) * 2,
             &g[(size_t)(row0 + row) * K + kt + c8 * 8]);
    }
}

template <int EPI>
__global__ __launch_bounds__(256, 2)
void gemm_f16_kernel(const __half* __restrict__ A, const __half* __restrict__ Bt,
                     const float* __restrict__ bias, const float* __restrict__ resid,
                     void* __restrict__ CoutV, int M, int N, int K) {
    extern __shared__ __half smh[];
    uint32_t sbase = smem_u32(smh);

    const int tid  = threadIdx.x;
    const int lane = tid & 31;
    const int warp = tid >> 5;
    const int wm = warp >> 2;        // 0..1 -> 64 M-rows
    const int wn = warp & 3;         // 0..3 -> 32 N-cols
    const int mb = blockIdx.y * 128;
    const int nb = blockIdx.x * 128;
    const int r = lane >> 2;
    const int c = lane & 3;

    float acc[4][4][4];
    #pragma unroll
    for (int mi = 0; mi < 4; mi++)
        #pragma unroll
        for (int ni = 0; ni < 4; ni++)
            #pragma unroll
            for (int j = 0; j < 4; j++) acc[mi][ni][j] = 0.0f;

    const int S = K >> 5;

    // prologue: stages 0,1
    load_tile_h(A,  mb, K, 0, sbase);
    load_tile_h(Bt, nb, K, 0, sbase + TILE_B);
    cp_commit();
    if (S > 1) {
        load_tile_h(A,  mb, K, 32, sbase + 2 * TILE_B);
        load_tile_h(Bt, nb, K, 32, sbase + 3 * TILE_B);
    }
    cp_commit();

    for (int s = 0; s < S; s++) {
        if (s < S - 1) cp_wait<1>(); else cp_wait<0>();
        __syncthreads();

        if (s + 2 < S) {
            int q = (s + 2) % NSTAGE;
            load_tile_h(A,  mb, K, (s + 2) << 5, sbase + (2 * q) * TILE_B);
            load_tile_h(Bt, nb, K, (s + 2) << 5, sbase + (2 * q + 1) * TILE_B);
        }
        cp_commit();

        int p = s % NSTAGE;
        const uint32_t* As32 = (const uint32_t*)(smh + (size_t)p * 2 * TILE_H);
        const uint32_t* Bs32 = (const uint32_t*)(smh + (size_t)(p * 2 + 1) * TILE_H);

        #pragma unroll
        for (int kk = 0; kk < 2; kk++) {     // k = kk*16
            const int kw = kk * 8 + c;       // word offset in row
            uint32_t afr[4][4];
            uint32_t bfr[4][2];
            #pragma unroll
            for (int mi = 0; mi < 4; mi++) {
                int m0 = wm * 64 + mi * 16;
                int base = (m0 + r) * (TS_H / 2) + kw;
                afr[mi][0] = As32[base];
                afr[mi][1] = As32[base + 8 * (TS_H / 2)];
                afr[mi][2] = As32[base + 4];
                afr[mi][3] = As32[base + 8 * (TS_H / 2) + 4];
            }
            #pragma unroll
            for (int ni = 0; ni < 4; ni++) {
                int col = wn * 32 + ni * 8 + r;
                int base = col * (TS_H / 2) + kw;
                bfr[ni][0] = Bs32[base];
                bfr[ni][1] = Bs32[base + 4];
            }
            #pragma unroll
            for (int mi = 0; mi < 4; mi++)
                #pragma unroll
                for (int ni = 0; ni < 4; ni++)
                    mma_f16(acc[mi][ni], afr[mi], bfr[ni]);
        }
    }
    __syncthreads();

    // epilogue
    #pragma unroll
    for (int mi = 0; mi < 4; mi++) {
        int row0 = mb + wm * 64 + mi * 16 + r;
        #pragma unroll
        for (int ni = 0; ni < 4; ni++) {
            int col0 = nb + wn * 32 + ni * 8 + 2 * c;
            float bs0 = bias[col0], bs1 = bias[col0 + 1];
            #pragma unroll
            for (int half = 0; half < 2; half++) {
                int row = row0 + half * 8;
                float v0 = acc[mi][ni][half * 2 + 0] + bs0;
                float v1 = acc[mi][ni][half * 2 + 1] + bs1;
                if (EPI == 0) {
                    __half2 hv = __floats2half2_rn(gelu_tanh(v0), gelu_tanh(v1));
                    *reinterpret_cast<__half2*>(&((__half*)CoutV)[(size_t)row * N + col0]) = hv;
                } else {
                    float2 rv = *reinterpret_cast<const float2*>(&resid[(size_t)row * N + col0]);
                    float2 o = make_float2(v0 + rv.x, v1 + rv.y);
                    *reinterpret_cast<float2*>(&((float*)CoutV)[(size_t)row * N + col0]) = o;
                }
            }
        }
    }
}

// ---------------- K3: path gating ----------------
__global__ __launch_bounds__(256)
void gate_kernel(const float* __restrict__ vtp, const float* __restrict__ dts,
                 const float* __restrict__ pg_g, const float* __restrict__ pg_b,
                 const float* __restrict__ gw, const float* __restrict__ gb,
                 float* __restrict__ out, float* __restrict__ gmem_out) {
    int t = blockIdx.x;
    __shared__ float4 z4[ZD / 4];
    __shared__ float red[32];
    __shared__ float sh5[NPATH];
    __shared__ float spi[NPATH];

    if (threadIdx.x < NPATH) sh5[threadIdx.x] = 0.0f;

    const float4* vtp4 = (const float4*)vtp;
    const float4* dts4 = (const float4*)dts;
    float lsum = 0.f, lsq = 0.f;
    #pragma unroll
    for (int i4 = threadIdx.x; i4 < ZD / 4; i4 += 256) {
        int p = i4 >> 8, d4 = i4 & 255;
        float4 v = (p == 0) ? vtp4[(size_t)t * 256 + d4]
                            : dts4[((size_t)(p - 1) * BT + t) * 256 + d4];
        z4[i4] = v;
        lsum += v.x + v.y + v.z + v.w;
        lsq  += v.x * v.x + v.y * v.y + v.z * v.z + v.w * v.w;
    }
    float s  = block_reduce_sum(lsum, red);
    float sq = block_reduce_sum(lsq,  red);
    float mu = s * (1.0f / ZD);
    float rs = rsqrtf(sq * (1.0f / ZD) - mu * mu + 1e-5f);

    const float4* g4 = (const float4*)pg_g;
    const float4* b4 = (const float4*)pg_b;
    const float4* gw4 = (const float4*)gw;
    float accp[NPATH] = {0.f, 0.f, 0.f, 0.f, 0.f};
    #pragma unroll
    for (int i4 = threadIdx.x; i4 < ZD / 4; i4 += 256) {
        float4 zv = z4[i4], gg = g4[i4], bb = b4[i4];
        float zn[4];
        zn[0] = (zv.x - mu) * rs * gg.x + bb.x;
        zn[1] = (zv.y - mu) * rs * gg.y + bb.y;
        zn[2] = (zv.z - mu) * rs * gg.z + bb.z;
        zn[3] = (zv.w - mu) * rs * gg.w + bb.w;
        float gwf[20];
        #pragma unroll
        for (int q = 0; q < 5; q++)
            *reinterpret_cast<float4*>(&gwf[q * 4]) = gw4[(size_t)i4 * 5 + q];
        #pragma unroll
        for (int e = 0; e < 4; e++)
            #pragma unroll
            for (int p = 0; p < NPATH; p++)
                accp[p] += zn[e] * gwf[e * 5 + p];
    }
    #pragma unroll
    for (int p = 0; p < NPATH; p++) {
        float v = accp[p];
        #pragma unroll
        for (int o = 16; o > 0; o >>= 1) v += __shfl_down_sync(0xffffffffu, v, o);
        if ((threadIdx.x & 31) == 0) atomicAdd(&sh5[p], v);
    }
    __syncthreads();

    if (threadIdx.x == 0) {
        float lg[NPATH];
        float mx = -1e30f;
        #pragma unroll
        for (int p = 0; p < NPATH; p++) { lg[p] = sh5[p] + gb[p]; mx = fmaxf(mx, lg[p]); }
        float ssum = 0.f;
        #pragma unroll
        for (int p = 0; p < NPATH; p++) { lg[p] = expf(lg[p] - mx); ssum += lg[p]; }
        float inv = 1.0f / ssum;
        #pragma unroll
        for (int p = 0; p < NPATH; p++) spi[p] = lg[p] * inv;
        gmem_out[t] = spi[1] + spi[2] + spi[3] + spi[4];
    }
    __syncthreads();

    float4* out4 = (float4*)out;
    #pragma unroll
    for (int d4 = threadIdx.x; d4 < DDIM / 4; d4 += 256) {
        float4 o = make_float4(0.f, 0.f, 0.f, 0.f);
        #pragma unroll
        for (int p = 0; p < NPATH; p++) {
            float4 zp = z4[p * (DDIM / 4) + d4];
            o.x += spi[p] * zp.x; o.y += spi[p] * zp.y;
            o.z += spi[p] * zp.z; o.w += spi[p] * zp.w;
        }
        out4[(size_t)t * (DDIM / 4) + d4] = o;
    }
}

// ---------------- launch ----------------
extern "C" void kernel_launch(void* const* d_in, const int* in_sizes, int n_in,
                              void* d_out, int out_size) {
    const float* x        = (const float*)d_in[0];
    const float* vt       = (const float*)d_in[1];
    const float* dts      = (const float*)d_in[2];
    const float* r_feat   = (const float*)d_in[3];
    const float* fln_g    = (const float*)d_in[4];
    const float* fln_b    = (const float*)d_in[5];
    const float* w1       = (const float*)d_in[6];
    const float* b1       = (const float*)d_in[7];
    const float* w2       = (const float*)d_in[8];
    const float* b2       = (const float*)d_in[9];
    const float* pg_g     = (const float*)d_in[10];
    const float* pg_b     = (const float*)d_in[11];
    const float* gw       = (const float*)d_in[12];
    const float* gb       = (const float*)d_in[13];

    float* out  = (float*)d_out;                  // [BT, D]
    float* gmem = out + (size_t)BT * DDIM;        // [BT]

    __half* abuf; cudaGetSymbolAddress((void**)&abuf, g_abuf);
    __half* hbuf; cudaGetSymbolAddress((void**)&hbuf, g_hbuf);
    float*  vtp;  cudaGetSymbolAddress((void**)&vtp,  g_vtp);
    __half* w1t;  cudaGetSymbolAddress((void**)&w1t,  g_w1t);
    __half* w2t;  cudaGetSymbolAddress((void**)&w2t,  g_w2t);

    cudaFuncSetAttribute(gemm_f16_kernel<0>, cudaFuncAttributeMaxDynamicSharedMemorySize, GEMM_SMEM);
    cudaFuncSetAttribute(gemm_f16_kernel<1>, cudaFuncAttributeMaxDynamicSharedMemorySize, GEMM_SMEM);

    // weight transposes + fp16: w1 [KF,HDIM] -> w1t [HDIM,KF]; w2 [HDIM,DDIM] -> w2t [DDIM,HDIM]
    {
        dim3 blk(32, 8);
        dim3 g1(HDIM / 32, KF / 32);
        transpose_h_kernel<<<g1, blk>>>(w1, w1t, KF, HDIM);
        dim3 g2(DDIM / 32, HDIM / 32);
        transpose_h_kernel<<<g2, blk>>>(w2, w2t, HDIM, DDIM);
    }

    // K0: LN(cat(x, r_feat)) -> abuf (fp16)
    ln_fuse_kernel<<<BT, 128>>>(x, r_feat, fln_g, fln_b, abuf);

    // K1: h = fp16(gelu(A @ W1 + b1))  [8192x1152]x[1152x4096]
    {
        dim3 grid(HDIM / 128, BT / 128);
        gemm_f16_kernel<0><<<grid, 256, GEMM_SMEM>>>(abuf, w1t, b1, nullptr, hbuf, BT, HDIM, KF);
    }
    // K2: vt' = h @ W2 + b2 + vt  [8192x4096]x[4096x1024]
    {
        dim3 grid(DDIM / 128, BT / 128);
        gemm_f16_kernel<1><<<grid, 256, GEMM_SMEM>>>(hbuf, w2t, b2, vt, vtp, BT, DDIM, HDIM);
    }
    // K3: gating + mix
    gate_kernel<<<BT, 256>>>(vtp, dts, pg_g, pg_b, gw, gb, out, gmem);
}

// round 5
// speedup vs baseline: 2.1425x; 1.0983x over previous
#include <cuda_runtime.h>
#include <cuda_fp16.h>
#include <math.h>
#include <stdint.h>

#define BT    8192      // B*T tokens
#define DDIM  1024
#define WRD   128
#define KF    1152      // D + WR
#define HDIM  4096
#define NPATH 5
#define ZD    5120      // NPATH * D

// ---------------- scratch (device globals; allocation-free) ----------------
__device__ __half g_abuf[BT * KF];                // LN(cat(x, r_feat)), fp16
__device__ __half g_hbuf[BT * HDIM];              // gelu(A@W1 + b1), fp16
__device__ float  g_vtp [BT * DDIM];              // vt + h@W2 + b2 (fp32)
__device__ __half g_w1t [HDIM * KF];              // w1^T [N,K] fp16
__device__ __half g_w2t [DDIM * HDIM];            // w2^T [N,K] fp16
__device__ float  g_gwt [NPATH * ZD];             // gate_w^T [5, 5120] fp32

// ---------------- helpers ----------------
__device__ __forceinline__ float gelu_tanh(float v) {
    float t = tanhf(0.7978845608028654f * (v + 0.044715f * v * v * v));
    return 0.5f * v * (1.0f + t);
}
__device__ __forceinline__ uint32_t smem_u32(const void* p) {
    uint32_t a;
    asm("{ .reg .u64 t; cvta.to.shared.u64 t, %1; cvt.u32.u64 %0, t; }" : "=r"(a) : "l"(p));
    return a;
}
__device__ __forceinline__ void mma_f16(float* d, const uint32_t* a, const uint32_t* b) {
    asm volatile(
        "mma.sync.aligned.m16n8k16.row.col.f32.f16.f16.f32 "
        "{%0,%1,%2,%3}, {%4,%5,%6,%7}, {%8,%9}, {%0,%1,%2,%3};"
        : "+f"(d[0]), "+f"(d[1]), "+f"(d[2]), "+f"(d[3])
        : "r"(a[0]), "r"(a[1]), "r"(a[2]), "r"(a[3]),
          "r"(b[0]), "r"(b[1]));
}
__device__ __forceinline__ void ldsm_x4(uint32_t* r, uint32_t addr) {
    asm volatile("ldmatrix.sync.aligned.m8n8.x4.shared.b16 {%0,%1,%2,%3}, [%4];"
        : "=r"(r[0]), "=r"(r[1]), "=r"(r[2]), "=r"(r[3]) : "r"(addr));
}
__device__ __forceinline__ void cp16(uint32_t dst, const void* src) {
    asm volatile("cp.async.cg.shared.global [%0], [%1], 16;" :: "r"(dst), "l"(src));
}
__device__ __forceinline__ void cp_commit() {
    asm volatile("cp.async.commit_group;" ::: "memory");
}
template <int N>
__device__ __forceinline__ void cp_wait() {
    asm volatile("cp.async.wait_group %0;" :: "n"(N) : "memory");
}
__device__ __forceinline__ float block_reduce_sum(float v, float* red) {
    #pragma unroll
    for (int o = 16; o > 0; o >>= 1) v += __shfl_down_sync(0xffffffffu, v, o);
    int lane = threadIdx.x & 31, w = threadIdx.x >> 5;
    int nw = (blockDim.x + 31) >> 5;
    if (lane == 0) red[w] = v;
    __syncthreads();
    if (w == 0) {
        v = (lane < nw) ? red[lane] : 0.0f;
        #pragma unroll
        for (int o = 16; o > 0; o >>= 1) v += __shfl_down_sync(0xffffffffu, v, o);
        if (lane == 0) red[0] = v;
    }
    __syncthreads();
    float r = red[0];
    __syncthreads();
    return r;
}

// ---------------- K-1a: transpose + fp16 (w [R,C] -> wt [C,R]) ----------------
__global__ void transpose_h_kernel(const float* __restrict__ in, __half* __restrict__ out,
                                   int R, int C) {
    __shared__ float tile[32][33];
    int bx = blockIdx.x * 32;   // C
    int by = blockIdx.y * 32;   // R
    int x = bx + threadIdx.x;
    #pragma unroll
    for (int j = threadIdx.y; j < 32; j += 8)
        tile[j][threadIdx.x] = in[(size_t)(by + j) * C + x];
    __syncthreads();
    int ox = by + threadIdx.x;
    #pragma unroll
    for (int j = threadIdx.y; j < 32; j += 8)
        out[(size_t)(bx + j) * R + ox] = __float2half_rn(tile[threadIdx.x][j]);
}

// ---------------- K-1b: gate_w [ZD,5] -> gwT [5,ZD] ----------------
__global__ void gwt_kernel(const float* __restrict__ gw, float* __restrict__ gwT) {
    int i = blockIdx.x * 256 + threadIdx.x;
    if (i < ZD) {
        #pragma unroll
        for (int p = 0; p < NPATH; p++)
            gwT[p * ZD + i] = gw[(size_t)i * NPATH + p];
    }
}

// ---------------- K0: LN of cat(x, r_feat) -> g_abuf (fp16) ----------------
__global__ __launch_bounds__(128)
void ln_fuse_kernel(const float* __restrict__ x, const float* __restrict__ rf,
                    const float* __restrict__ g, const float* __restrict__ b,
                    __half* __restrict__ out) {
    int t = blockIdx.x;
    __shared__ float4 sv4[KF / 4];
    __shared__ float red[32];
    const float4* x4  = (const float4*)x;
    const float4* rf4 = (const float4*)rf;
    float lsum = 0.f, lsq = 0.f;
    #pragma unroll
    for (int i4 = threadIdx.x; i4 < KF / 4; i4 += 128) {
        float4 v = (i4 < DDIM / 4) ? x4[(size_t)t * (DDIM / 4) + i4]
                                   : rf4[(size_t)t * (WRD / 4) + (i4 - DDIM / 4)];
        sv4[i4] = v;
        lsum += v.x + v.y + v.z + v.w;
        lsq  += v.x * v.x + v.y * v.y + v.z * v.z + v.w * v.w;
    }
    float s  = block_reduce_sum(lsum, red);
    float sq = block_reduce_sum(lsq,  red);
    float mu = s * (1.0f / KF);
    float rs = rsqrtf(sq * (1.0f / KF) - mu * mu + 1e-5f);
    const float4* g4 = (const float4*)g;
    const float4* b4 = (const float4*)b;
    uint2* o4 = (uint2*)out;
    #pragma unroll
    for (int i4 = threadIdx.x; i4 < KF / 4; i4 += 128) {
        float4 v = sv4[i4], gg = g4[i4], bb = b4[i4];
        __half2 h01 = __floats2half2_rn((v.x - mu) * rs * gg.x + bb.x,
                                        (v.y - mu) * rs * gg.y + bb.y);
        __half2 h23 = __floats2half2_rn((v.z - mu) * rs * gg.z + bb.z,
                                        (v.w - mu) * rs * gg.w + bb.w);
        uint2 o;
        o.x = *reinterpret_cast<uint32_t*>(&h01);
        o.y = *reinterpret_cast<uint32_t*>(&h23);
        o4[(size_t)t * (KF / 4) + i4] = o;
    }
}

// ---------------- fp16 mma.sync GEMM, 3-stage cp.async + ldmatrix ----------------
// C[M,N] = A[M,K] @ Bt[N,K]^T, fp16 operands, fp32 accum.
// CTA tile 128(M) x 128(N), BK=32. 8 warps as 2(M) x 4(N): warp tile 64x32.
#define TS_H   40                 // halfs per smem tile row (20 words; conflict-free)
#define TILE_H (128 * TS_H)       // halfs per tile
#define TILE_B (TILE_H * 2)       // 10240 bytes
#define NSTAGE 3
#define GEMM_SMEM (NSTAGE * 2 * TILE_B)

// load 128 rows x 32 halfs from g[(row0+row)*K + kt ...]
__device__ __forceinline__ void load_tile_h(const __half* __restrict__ g, int row0, int K,
                                            int kt, uint32_t sm) {
    int tid = threadIdx.x;
    #pragma unroll
    for (int i = 0; i < 2; i++) {
        int lin = tid + i * 256;
        int row = lin >> 2, c8 = lin & 3;
        cp16(sm + (uint32_t)(row * TS_H + c8 * 8) * 2,
             &g[(size_t)(row0 + row) * K + kt + c8 * 8]);
    }
}

template <int EPI>
__global__ __launch_bounds__(256, 2)
void gemm_f16_kernel(const __half* __restrict__ A, const __half* __restrict__ Bt,
                     const float* __restrict__ bias, const float* __restrict__ resid,
                     void* __restrict__ CoutV, int M, int N, int K) {
    extern __shared__ __half smh[];
    uint32_t sbase = smem_u32(smh);

    const int tid  = threadIdx.x;
    const int lane = tid & 31;
    const int warp = tid >> 5;
    const int wm = warp >> 2;        // 0..1 -> 64 M-rows
    const int wn = warp & 3;         // 0..3 -> 32 N-cols
    const int mb = blockIdx.y * 128;
    const int nb = blockIdx.x * 128;
    const int r = lane >> 2;
    const int c = lane & 3;

    // ldmatrix per-lane byte offsets (within a tile)
    uint32_t offA[4], offB[2];
    #pragma unroll
    for (int mi = 0; mi < 4; mi++) {
        int row = wm * 64 + mi * 16 + (lane & 15);
        offA[mi] = (uint32_t)(row * TS_H + ((lane >> 4) & 1) * 8) * 2;
    }
    #pragma unroll
    for (int np = 0; np < 2; np++) {
        int row = wn * 32 + np * 16 + ((lane >> 4) & 1) * 8 + (lane & 7);
        offB[np] = (uint32_t)(row * TS_H + ((lane >> 3) & 1) * 8) * 2;
    }

    float acc[4][4][4];
    #pragma unroll
    for (int mi = 0; mi < 4; mi++)
        #pragma unroll
        for (int ni = 0; ni < 4; ni++)
            #pragma unroll
            for (int j = 0; j < 4; j++) acc[mi][ni][j] = 0.0f;

    const int S = K >> 5;

    // prologue: stages 0,1
    load_tile_h(A,  mb, K, 0, sbase);
    load_tile_h(Bt, nb, K, 0, sbase + TILE_B);
    cp_commit();
    if (S > 1) {
        load_tile_h(A,  mb, K, 32, sbase + 2 * TILE_B);
        load_tile_h(Bt, nb, K, 32, sbase + 3 * TILE_B);
    }
    cp_commit();

    int p = 0;
    for (int s = 0; s < S; s++) {
        if (s < S - 1) cp_wait<1>(); else cp_wait<0>();
        __syncthreads();

        if (s + 2 < S) {
            int q = p + 2; if (q >= NSTAGE) q -= NSTAGE;
            load_tile_h(A,  mb, K, (s + 2) << 5, sbase + (2 * q) * TILE_B);
            load_tile_h(Bt, nb, K, (s + 2) << 5, sbase + (2 * q + 1) * TILE_B);
        }
        cp_commit();

        uint32_t abase = sbase + (2 * p) * TILE_B;
        uint32_t bbase = abase + TILE_B;

        #pragma unroll
        for (int kk = 0; kk < 2; kk++) {     // k = kk*16
            uint32_t koff = (uint32_t)kk * 32;   // 16 halfs = 32 bytes
            uint32_t afr[4][4];
            uint32_t bfr[2][4];
            #pragma unroll
            for (int mi = 0; mi < 4; mi++) ldsm_x4(afr[mi], abase + offA[mi] + koff);
            #pragma unroll
            for (int np = 0; np < 2; np++) ldsm_x4(bfr[np], bbase + offB[np] + koff);
            #pragma unroll
            for (int mi = 0; mi < 4; mi++)
                #pragma unroll
                for (int ni = 0; ni < 4; ni++)
                    mma_f16(acc[mi][ni], afr[mi], &bfr[ni >> 1][(ni & 1) * 2]);
        }
        p++; if (p >= NSTAGE) p -= NSTAGE;
    }
    __syncthreads();

    // epilogue
    #pragma unroll
    for (int mi = 0; mi < 4; mi++) {
        int row0 = mb + wm * 64 + mi * 16 + r;
        #pragma unroll
        for (int ni = 0; ni < 4; ni++) {
            int col0 = nb + wn * 32 + ni * 8 + 2 * c;
            float bs0 = bias[col0], bs1 = bias[col0 + 1];
            #pragma unroll
            for (int half = 0; half < 2; half++) {
                int row = row0 + half * 8;
                float v0 = acc[mi][ni][half * 2 + 0] + bs0;
                float v1 = acc[mi][ni][half * 2 + 1] + bs1;
                if (EPI == 0) {
                    __half2 hv = __floats2half2_rn(gelu_tanh(v0), gelu_tanh(v1));
                    *reinterpret_cast<__half2*>(&((__half*)CoutV)[(size_t)row * N + col0]) = hv;
                } else {
                    float2 rv = *reinterpret_cast<const float2*>(&resid[(size_t)row * N + col0]);
                    float2 o = make_float2(v0 + rv.x, v1 + rv.y);
                    *reinterpret_cast<float2*>(&((float*)CoutV)[(size_t)row * N + col0]) = o;
                }
            }
        }
    }
}

// ---------------- K3: path gating (4 tokens / block) ----------------
#define GTOK 4
#define Z4PT (ZD / 4)            // 1280 float4 per token
__global__ __launch_bounds__(256)
void gate_kernel(const float* __restrict__ vtp, const float* __restrict__ dts,
                 const float* __restrict__ pg_g, const float* __restrict__ pg_b,
                 const float* __restrict__ gwT, const float* __restrict__ gb,
                 float* __restrict__ out, float* __restrict__ gmem_out) {
    extern __shared__ float4 z4s[];      // [GTOK][Z4PT] = 80 KB
    __shared__ float red[32];
    __shared__ float sh5[GTOK][NPATH];
    __shared__ float spi[GTOK][NPATH];

    const int tid = threadIdx.x;
    const int t0 = blockIdx.x * GTOK;
    if (tid < GTOK * NPATH) ((float*)sh5)[tid] = 0.0f;

    const float4* vtp4 = (const float4*)vtp;
    const float4* dts4 = (const float4*)dts;

    // load z for 4 tokens into smem
    #pragma unroll
    for (int lin = tid; lin < GTOK * Z4PT; lin += 256) {
        int tok = lin / Z4PT, i4 = lin - tok * Z4PT;
        int t = t0 + tok;
        int p = i4 >> 8, d4 = i4 & 255;
        float4 v = (p == 0) ? vtp4[(size_t)t * 256 + d4]
                            : dts4[((size_t)(p - 1) * BT + t) * 256 + d4];
        z4s[tok * Z4PT + i4] = v;
    }
    __syncthreads();

    // per-token stats
    float mu4[GTOK], rs4[GTOK];
    #pragma unroll
    for (int tok = 0; tok < GTOK; tok++) {
        float ls = 0.f, lq = 0.f;
        #pragma unroll
        for (int i4 = tid; i4 < Z4PT; i4 += 256) {
            float4 v = z4s[tok * Z4PT + i4];
            ls += v.x + v.y + v.z + v.w;
            lq += v.x * v.x + v.y * v.y + v.z * v.z + v.w * v.w;
        }
        float s = block_reduce_sum(ls, red);
        float q = block_reduce_sum(lq, red);
        mu4[tok] = s * (1.0f / ZD);
        rs4[tok] = rsqrtf(q * (1.0f / ZD) - mu4[tok] * mu4[tok] + 1e-5f);
    }

    // logits: coalesced gwT loads, reused across 4 tokens
    const float4* g4  = (const float4*)pg_g;
    const float4* b4  = (const float4*)pg_b;
    const float4* gwT4 = (const float4*)gwT;    // [5][1280] float4
    float accp[GTOK][NPATH];
    #pragma unroll
    for (int tok = 0; tok < GTOK; tok++)
        #pragma unroll
        for (int pp = 0; pp < NPATH; pp++) accp[tok][pp] = 0.f;

    #pragma unroll
    for (int it = 0; it < Z4PT / 256; it++) {   // 5 iters
        int i4 = tid + it * 256;
        float4 gwf[NPATH];
        #pragma unroll
        for (int pp = 0; pp < NPATH; pp++) gwf[pp] = gwT4[pp * Z4PT + i4];
        float4 gg = g4[i4], bb = b4[i4];
        #pragma unroll
        for (int tok = 0; tok < GTOK; tok++) {
            float4 zv = z4s[tok * Z4PT + i4];
            float mu = mu4[tok], rs = rs4[tok];
            float zn0 = (zv.x - mu) * rs * gg.x + bb.x;
            float zn1 = (zv.y - mu) * rs * gg.y + bb.y;
            float zn2 = (zv.z - mu) * rs * gg.z + bb.z;
            float zn3 = (zv.w - mu) * rs * gg.w + bb.w;
            #pragma unroll
            for (int pp = 0; pp < NPATH; pp++)
                accp[tok][pp] += zn0 * gwf[pp].x + zn1 * gwf[pp].y
                               + zn2 * gwf[pp].z + zn3 * gwf[pp].w;
        }
    }
    #pragma unroll
    for (int tok = 0; tok < GTOK; tok++)
        #pragma unroll
        for (int pp = 0; pp < NPATH; pp++) {
            float v = accp[tok][pp];
            #pragma unroll
            for (int o = 16; o > 0; o >>= 1) v += __shfl_down_sync(0xffffffffu, v, o);
            if ((tid & 31) == 0) atomicAdd(&sh5[tok][pp], v);
        }
    __syncthreads();

    if (tid < GTOK) {
        int tok = tid;
        float lg[NPATH];
        float mx = -1e30f;
        #pragma unroll
        for (int pp = 0; pp < NPATH; pp++) { lg[pp] = sh5[tok][pp] + gb[pp]; mx = fmaxf(mx, lg[pp]); }
        float ssum = 0.f;
        #pragma unroll
        for (int pp = 0; pp < NPATH; pp++) { lg[pp] = expf(lg[pp] - mx); ssum += lg[pp]; }
        float inv = 1.0f / ssum;
        #pragma unroll
        for (int pp = 0; pp < NPATH; pp++) spi[tok][pp] = lg[pp] * inv;
        gmem_out[t0 + tok] = spi[tok][1] + spi[tok][2] + spi[tok][3] + spi[tok][4];
    }
    __syncthreads();

    float4* out4 = (float4*)out;
    #pragma unroll
    for (int lin = tid; lin < GTOK * (DDIM / 4); lin += 256) {
        int tok = lin >> 8, d4 = lin & 255;
        float4 o = make_float4(0.f, 0.f, 0.f, 0.f);
        #pragma unroll
        for (int pp = 0; pp < NPATH; pp++) {
            float4 zp = z4s[tok * Z4PT + pp * 256 + d4];
            float w = spi[tok][pp];
            o.x += w * zp.x; o.y += w * zp.y; o.z += w * zp.z; o.w += w * zp.w;
        }
        out4[(size_t)(t0 + tok) * 256 + d4] = o;
    }
}
#define GATE_SMEM (GTOK * Z4PT * 16)

// ---------------- launch ----------------
extern "C" void kernel_launch(void* const* d_in, const int* in_sizes, int n_in,
                              void* d_out, int out_size) {
    const float* x        = (const float*)d_in[0];
    const float* vt       = (const float*)d_in[1];
    const float* dts      = (const float*)d_in[2];
    const float* r_feat   = (const float*)d_in[3];
    const float* fln_g    = (const float*)d_in[4];
    const float* fln_b    = (const float*)d_in[5];
    const float* w1       = (const float*)d_in[6];
    const float* b1       = (const float*)d_in[7];
    const float* w2       = (const float*)d_in[8];
    const float* b2       = (const float*)d_in[9];
    const float* pg_g     = (const float*)d_in[10];
    const float* pg_b     = (const float*)d_in[11];
    const float* gw       = (const float*)d_in[12];
    const float* gb       = (const float*)d_in[13];

    float* out  = (float*)d_out;                  // [BT, D]
    float* gmem = out + (size_t)BT * DDIM;        // [BT]

    __half* abuf; cudaGetSymbolAddress((void**)&abuf, g_abuf);
    __half* hbuf; cudaGetSymbolAddress((void**)&hbuf, g_hbuf);
    float*  vtp;  cudaGetSymbolAddress((void**)&vtp,  g_vtp);
    __half* w1t;  cudaGetSymbolAddress((void**)&w1t,  g_w1t);
    __half* w2t;  cudaGetSymbolAddress((void**)&w2t,  g_w2t);
    float*  gwt;  cudaGetSymbolAddress((void**)&gwt,  g_gwt);

    cudaFuncSetAttribute(gemm_f16_kernel<0>, cudaFuncAttributeMaxDynamicSharedMemorySize, GEMM_SMEM);
    cudaFuncSetAttribute(gemm_f16_kernel<1>, cudaFuncAttributeMaxDynamicSharedMemorySize, GEMM_SMEM);
    cudaFuncSetAttribute(gate_kernel, cudaFuncAttributeMaxDynamicSharedMemorySize, GATE_SMEM);

    // weight transposes + fp16; gate_w transpose
    {
        dim3 blk(32, 8);
        dim3 g1(HDIM / 32, KF / 32);
        transpose_h_kernel<<<g1, blk>>>(w1, w1t, KF, HDIM);
        dim3 g2(DDIM / 32, HDIM / 32);
        transpose_h_kernel<<<g2, blk>>>(w2, w2t, HDIM, DDIM);
        gwt_kernel<<<(ZD + 255) / 256, 256>>>(gw, gwt);
    }

    // K0: LN(cat(x, r_feat)) -> abuf (fp16)
    ln_fuse_kernel<<<BT, 128>>>(x, r_feat, fln_g, fln_b, abuf);

    // K1: h = fp16(gelu(A @ W1 + b1))  [8192x1152]x[1152x4096]
    {
        dim3 grid(HDIM / 128, BT / 128);
        gemm_f16_kernel<0><<<grid, 256, GEMM_SMEM>>>(abuf, w1t, b1, nullptr, hbuf, BT, HDIM, KF);
    }
    // K2: vt' = h @ W2 + b2 + vt  [8192x4096]x[4096x1024]
    {
        dim3 grid(DDIM / 128, BT / 128);
        gemm_f16_kernel<1><<<grid, 256, GEMM_SMEM>>>(hbuf, w2t, b2, vt, vtp, BT, DDIM, HDIM);
    }
    // K3: gating + mix
    gate_kernel<<<BT / GTOK, 256, GATE_SMEM>>>(vtp, dts, pg_g, pg_b, gwt, gb, out, gmem);
}

// round 6
// speedup vs baseline: 2.2269x; 1.0394x over previous
#include <cuda_runtime.h>
#include <cuda_fp16.h>
#include <math.h>
#include <stdint.h>

#define BT    8192      // B*T tokens
#define DDIM  1024
#define WRD   128
#define KF    1152      // D + WR
#define HDIM  4096
#define NPATH 5
#define ZD    5120      // NPATH * D

// ---------------- scratch (device globals; allocation-free) ----------------
__device__ __half g_abuf[BT * KF];                // LN(cat(x, r_feat)), fp16
__device__ __half g_hbuf[BT * HDIM];              // gelu(A@W1 + b1), fp16
__device__ float  g_vtp [BT * DDIM];              // vt + h@W2 + b2 (fp32)
__device__ __half g_w1t [HDIM * KF];              // w1^T [N,K] fp16
__device__ __half g_w2t [DDIM * HDIM];            // w2^T [N,K] fp16
__device__ float  g_gwt [NPATH * ZD];             // gate_w^T [5, 5120] fp32

// ---------------- helpers ----------------
__device__ __forceinline__ float gelu_tanh(float v) {
    float t = tanhf(0.7978845608028654f * (v + 0.044715f * v * v * v));
    return 0.5f * v * (1.0f + t);
}
__device__ __forceinline__ uint32_t smem_u32(const void* p) {
    uint32_t a;
    asm("{ .reg .u64 t; cvta.to.shared.u64 t, %1; cvt.u32.u64 %0, t; }" : "=r"(a) : "l"(p));
    return a;
}
__device__ __forceinline__ void mma_f16(float* d, const uint32_t* a, const uint32_t* b) {
    asm volatile(
        "mma.sync.aligned.m16n8k16.row.col.f32.f16.f16.f32 "
        "{%0,%1,%2,%3}, {%4,%5,%6,%7}, {%8,%9}, {%0,%1,%2,%3};"
        : "+f"(d[0]), "+f"(d[1]), "+f"(d[2]), "+f"(d[3])
        : "r"(a[0]), "r"(a[1]), "r"(a[2]), "r"(a[3]),
          "r"(b[0]), "r"(b[1]));
}
__device__ __forceinline__ void ldsm_x4(uint32_t* r, uint32_t addr) {
    asm volatile("ldmatrix.sync.aligned.m8n8.x4.shared.b16 {%0,%1,%2,%3}, [%4];"
        : "=r"(r[0]), "=r"(r[1]), "=r"(r[2]), "=r"(r[3]) : "r"(addr));
}
__device__ __forceinline__ void cp16(uint32_t dst, const void* src) {
    asm volatile("cp.async.cg.shared.global [%0], [%1], 16;" :: "r"(dst), "l"(src));
}
__device__ __forceinline__ void cp_commit() {
    asm volatile("cp.async.commit_group;" ::: "memory");
}
template <int N>
__device__ __forceinline__ void cp_wait() {
    asm volatile("cp.async.wait_group %0;" :: "n"(N) : "memory");
}
__device__ __forceinline__ float block_reduce_sum(float v, float* red) {
    #pragma unroll
    for (int o = 16; o > 0; o >>= 1) v += __shfl_down_sync(0xffffffffu, v, o);
    int lane = threadIdx.x & 31, w = threadIdx.x >> 5;
    int nw = (blockDim.x + 31) >> 5;
    if (lane == 0) red[w] = v;
    __syncthreads();
    if (w == 0) {
        v = (lane < nw) ? red[lane] : 0.0f;
        #pragma unroll
        for (int o = 16; o > 0; o >>= 1) v += __shfl_down_sync(0xffffffffu, v, o);
        if (lane == 0) red[0] = v;
    }
    __syncthreads();
    float r = red[0];
    __syncthreads();
    return r;
}

// ---------------- K-1a: transpose + fp16 (w [R,C] -> wt [C,R]) ----------------
__global__ void transpose_h_kernel(const float* __restrict__ in, __half* __restrict__ out,
                                   int R, int C) {
    __shared__ float tile[32][33];
    int bx = blockIdx.x * 32;   // C
    int by = blockIdx.y * 32;   // R
    int x = bx + threadIdx.x;
    #pragma unroll
    for (int j = threadIdx.y; j < 32; j += 8)
        tile[j][threadIdx.x] = in[(size_t)(by + j) * C + x];
    __syncthreads();
    int ox = by + threadIdx.x;
    #pragma unroll
    for (int j = threadIdx.y; j < 32; j += 8)
        out[(size_t)(bx + j) * R + ox] = __float2half_rn(tile[threadIdx.x][j]);
}

// ---------------- K-1b: gate_w [ZD,5] -> gwT [5,ZD] ----------------
__global__ void gwt_kernel(const float* __restrict__ gw, float* __restrict__ gwT) {
    int i = blockIdx.x * 256 + threadIdx.x;
    if (i < ZD) {
        #pragma unroll
        for (int p = 0; p < NPATH; p++)
            gwT[p * ZD + i] = gw[(size_t)i * NPATH + p];
    }
}

// ---------------- K0: LN of cat(x, r_feat) -> g_abuf (fp16) ----------------
__global__ __launch_bounds__(128)
void ln_fuse_kernel(const float* __restrict__ x, const float* __restrict__ rf,
                    const float* __restrict__ g, const float* __restrict__ b,
                    __half* __restrict__ out) {
    int t = blockIdx.x;
    __shared__ float4 sv4[KF / 4];
    __shared__ float red[32];
    const float4* x4  = (const float4*)x;
    const float4* rf4 = (const float4*)rf;
    float lsum = 0.f, lsq = 0.f;
    #pragma unroll
    for (int i4 = threadIdx.x; i4 < KF / 4; i4 += 128) {
        float4 v = (i4 < DDIM / 4) ? x4[(size_t)t * (DDIM / 4) + i4]
                                   : rf4[(size_t)t * (WRD / 4) + (i4 - DDIM / 4)];
        sv4[i4] = v;
        lsum += v.x + v.y + v.z + v.w;
        lsq  += v.x * v.x + v.y * v.y + v.z * v.z + v.w * v.w;
    }
    float s  = block_reduce_sum(lsum, red);
    float sq = block_reduce_sum(lsq,  red);
    float mu = s * (1.0f / KF);
    float rs = rsqrtf(sq * (1.0f / KF) - mu * mu + 1e-5f);
    const float4* g4 = (const float4*)g;
    const float4* b4 = (const float4*)b;
    uint2* o4 = (uint2*)out;
    #pragma unroll
    for (int i4 = threadIdx.x; i4 < KF / 4; i4 += 128) {
        float4 v = sv4[i4], gg = g4[i4], bb = b4[i4];
        __half2 h01 = __floats2half2_rn((v.x - mu) * rs * gg.x + bb.x,
                                        (v.y - mu) * rs * gg.y + bb.y);
        __half2 h23 = __floats2half2_rn((v.z - mu) * rs * gg.z + bb.z,
                                        (v.w - mu) * rs * gg.w + bb.w);
        uint2 o;
        o.x = *reinterpret_cast<uint32_t*>(&h01);
        o.y = *reinterpret_cast<uint32_t*>(&h23);
        o4[(size_t)t * (KF / 4) + i4] = o;
    }
}

// ---------------- fp16 mma.sync GEMM, BK=64, 3-stage cp.async + ldmatrix ----------------
// C[M,N] = A[M,K] @ Bt[N,K]^T, fp16 operands, fp32 accum.
// CTA tile 128(M) x 128(N), BK=64. 8 warps as 2(M) x 4(N): warp tile 64x32.
#define TS_H   72                 // halfs per smem tile row (36 words; ldmatrix conflict-free)
#define TILE_H (128 * TS_H)       // halfs per tile
#define TILE_B (TILE_H * 2)       // 18432 bytes
#define NSTAGE 3
#define GEMM_SMEM (NSTAGE * 2 * TILE_B)

// load 128 rows x 64 halfs from g[(row0+row)*K + kt ...]
__device__ __forceinline__ void load_tile_h(const __half* __restrict__ g, int row0, int K,
                                            int kt, uint32_t sm) {
    int tid = threadIdx.x;
    #pragma unroll
    for (int i = 0; i < 4; i++) {
        int lin = tid + i * 256;
        int row = lin >> 3, c8 = lin & 7;
        cp16(sm + (uint32_t)(row * TS_H + c8 * 8) * 2,
             &g[(size_t)(row0 + row) * K + kt + c8 * 8]);
    }
}

template <int EPI>
__global__ __launch_bounds__(256, 2)
void gemm_f16_kernel(const __half* __restrict__ A, const __half* __restrict__ Bt,
                     const float* __restrict__ bias, const float* __restrict__ resid,
                     void* __restrict__ CoutV, int M, int N, int K) {
    extern __shared__ __half smh[];
    uint32_t sbase = smem_u32(smh);

    const int tid  = threadIdx.x;
    const int lane = tid & 31;
    const int warp = tid >> 5;
    const int wm = warp >> 2;        // 0..1 -> 64 M-rows
    const int wn = warp & 3;         // 0..3 -> 32 N-cols
    const int mb = blockIdx.y * 128;
    const int nb = blockIdx.x * 128;
    const int r = lane >> 2;
    const int c = lane & 3;

    // ldmatrix per-lane byte offsets (within a tile)
    uint32_t offA[4], offB[2];
    #pragma unroll
    for (int mi = 0; mi < 4; mi++) {
        int row = wm * 64 + mi * 16 + (lane & 15);
        offA[mi] = (uint32_t)(row * TS_H + ((lane >> 4) & 1) * 8) * 2;
    }
    #pragma unroll
    for (int np = 0; np < 2; np++) {
        int row = wn * 32 + np * 16 + ((lane >> 4) & 1) * 8 + (lane & 7);
        offB[np] = (uint32_t)(row * TS_H + ((lane >> 3) & 1) * 8) * 2;
    }

    float acc[4][4][4];
    #pragma unroll
    for (int mi = 0; mi < 4; mi++)
        #pragma unroll
        for (int ni = 0; ni < 4; ni++)
            #pragma unroll
            for (int j = 0; j < 4; j++) acc[mi][ni][j] = 0.0f;

    const int S = K >> 6;

    // prologue: stages 0,1
    load_tile_h(A,  mb, K, 0, sbase);
    load_tile_h(Bt, nb, K, 0, sbase + TILE_B);
    cp_commit();
    if (S > 1) {
        load_tile_h(A,  mb, K, 64, sbase + 2 * TILE_B);
        load_tile_h(Bt, nb, K, 64, sbase + 3 * TILE_B);
    }
    cp_commit();

    uint32_t afr[2][4][4];
    uint32_t bfr[2][2][4];

    int p = 0;
    for (int s = 0; s < S; s++) {
        if (s < S - 1) cp_wait<1>(); else cp_wait<0>();
        __syncthreads();

        if (s + 2 < S) {
            int q = p + 2; if (q >= NSTAGE) q -= NSTAGE;
            load_tile_h(A,  mb, K, (s + 2) << 6, sbase + (2 * q) * TILE_B);
            load_tile_h(Bt, nb, K, (s + 2) << 6, sbase + (2 * q + 1) * TILE_B);
        }
        cp_commit();

        uint32_t abase = sbase + (2 * p) * TILE_B;
        uint32_t bbase = abase + TILE_B;

        // preload kk=0 fragments
        #pragma unroll
        for (int mi = 0; mi < 4; mi++) ldsm_x4(afr[0][mi], abase + offA[mi]);
        #pragma unroll
        for (int np = 0; np < 2; np++) ldsm_x4(bfr[0][np], bbase + offB[np]);

        #pragma unroll
        for (int kk = 0; kk < 4; kk++) {     // k = kk*16
            int cur = kk & 1, nxt = cur ^ 1;
            if (kk < 3) {
                uint32_t koff = (uint32_t)(kk + 1) * 32;   // 16 halfs = 32 bytes
                #pragma unroll
                for (int mi = 0; mi < 4; mi++) ldsm_x4(afr[nxt][mi], abase + offA[mi] + koff);
                #pragma unroll
                for (int np = 0; np < 2; np++) ldsm_x4(bfr[nxt][np], bbase + offB[np] + koff);
            }
            #pragma unroll
            for (int mi = 0; mi < 4; mi++)
                #pragma unroll
                for (int ni = 0; ni < 4; ni++)
                    mma_f16(acc[mi][ni], afr[cur][mi], &bfr[cur][ni >> 1][(ni & 1) * 2]);
        }
        p++; if (p >= NSTAGE) p -= NSTAGE;
    }
    __syncthreads();

    // epilogue
    #pragma unroll
    for (int mi = 0; mi < 4; mi++) {
        int row0 = mb + wm * 64 + mi * 16 + r;
        #pragma unroll
        for (int ni = 0; ni < 4; ni++) {
            int col0 = nb + wn * 32 + ni * 8 + 2 * c;
            float bs0 = bias[col0], bs1 = bias[col0 + 1];
            #pragma unroll
            for (int half = 0; half < 2; half++) {
                int row = row0 + half * 8;
                float v0 = acc[mi][ni][half * 2 + 0] + bs0;
                float v1 = acc[mi][ni][half * 2 + 1] + bs1;
                if (EPI == 0) {
                    __half2 hv = __floats2half2_rn(gelu_tanh(v0), gelu_tanh(v1));
                    *reinterpret_cast<__half2*>(&((__half*)CoutV)[(size_t)row * N + col0]) = hv;
                } else {
                    float2 rv = *reinterpret_cast<const float2*>(&resid[(size_t)row * N + col0]);
                    float2 o = make_float2(v0 + rv.x, v1 + rv.y);
                    *reinterpret_cast<float2*>(&((float*)CoutV)[(size_t)row * N + col0]) = o;
                }
            }
        }
    }
}

// ---------------- K3: path gating (4 tokens / block) ----------------
#define GTOK 4
#define Z4PT (ZD / 4)            // 1280 float4 per token
__global__ __launch_bounds__(256)
void gate_kernel(const float* __restrict__ vtp, const float* __restrict__ dts,
                 const float* __restrict__ pg_g, const float* __restrict__ pg_b,
                 const float* __restrict__ gwT, const float* __restrict__ gb,
                 float* __restrict__ out, float* __restrict__ gmem_out) {
    extern __shared__ float4 z4s[];      // [GTOK][Z4PT] = 80 KB
    __shared__ float red[32];
    __shared__ float sh5[GTOK][NPATH];
    __shared__ float spi[GTOK][NPATH];

    const int tid = threadIdx.x;
    const int t0 = blockIdx.x * GTOK;
    if (tid < GTOK * NPATH) ((float*)sh5)[tid] = 0.0f;

    const float4* vtp4 = (const float4*)vtp;
    const float4* dts4 = (const float4*)dts;

    // load z for 4 tokens into smem
    #pragma unroll
    for (int lin = tid; lin < GTOK * Z4PT; lin += 256) {
        int tok = lin / Z4PT, i4 = lin - tok * Z4PT;
        int t = t0 + tok;
        int p = i4 >> 8, d4 = i4 & 255;
        float4 v = (p == 0) ? vtp4[(size_t)t * 256 + d4]
                            : dts4[((size_t)(p - 1) * BT + t) * 256 + d4];
        z4s[tok * Z4PT + i4] = v;
    }
    __syncthreads();

    // per-token stats
    float mu4[GTOK], rs4[GTOK];
    #pragma unroll
    for (int tok = 0; tok < GTOK; tok++) {
        float ls = 0.f, lq = 0.f;
        #pragma unroll
        for (int i4 = tid; i4 < Z4PT; i4 += 256) {
            float4 v = z4s[tok * Z4PT + i4];
            ls += v.x + v.y + v.z + v.w;
            lq += v.x * v.x + v.y * v.y + v.z * v.z + v.w * v.w;
        }
        float s = block_reduce_sum(ls, red);
        float q = block_reduce_sum(lq, red);
        mu4[tok] = s * (1.0f / ZD);
        rs4[tok] = rsqrtf(q * (1.0f / ZD) - mu4[tok] * mu4[tok] + 1e-5f);
    }

    // logits: coalesced gwT loads, reused across 4 tokens
    const float4* g4  = (const float4*)pg_g;
    const float4* b4  = (const float4*)pg_b;
    const float4* gwT4 = (const float4*)gwT;    // [5][1280] float4
    float accp[GTOK][NPATH];
    #pragma unroll
    for (int tok = 0; tok < GTOK; tok++)
        #pragma unroll
        for (int pp = 0; pp < NPATH; pp++) accp[tok][pp] = 0.f;

    #pragma unroll
    for (int it = 0; it < Z4PT / 256; it++) {   // 5 iters
        int i4 = tid + it * 256;
        float4 gwf[NPATH];
        #pragma unroll
        for (int pp = 0; pp < NPATH; pp++) gwf[pp] = gwT4[pp * Z4PT + i4];
        float4 gg = g4[i4], bb = b4[i4];
        #pragma unroll
        for (int tok = 0; tok < GTOK; tok++) {
            float4 zv = z4s[tok * Z4PT + i4];
            float mu = mu4[tok], rs = rs4[tok];
            float zn0 = (zv.x - mu) * rs * gg.x + bb.x;
            float zn1 = (zv.y - mu) * rs * gg.y + bb.y;
            float zn2 = (zv.z - mu) * rs * gg.z + bb.z;
            float zn3 = (zv.w - mu) * rs * gg.w + bb.w;
            #pragma unroll
            for (int pp = 0; pp < NPATH; pp++)
                accp[tok][pp] += zn0 * gwf[pp].x + zn1 * gwf[pp].y
                               + zn2 * gwf[pp].z + zn3 * gwf[pp].w;
        }
    }
    #pragma unroll
    for (int tok = 0; tok < GTOK; tok++)
        #pragma unroll
        for (int pp = 0; pp < NPATH; pp++) {
            float v = accp[tok][pp];
            #pragma unroll
            for (int o = 16; o > 0; o >>= 1) v += __shfl_down_sync(0xffffffffu, v, o);
            if ((tid & 31) == 0) atomicAdd(&sh5[tok][pp], v);
        }
    __syncthreads();

    if (tid < GTOK) {
        int tok = tid;
        float lg[NPATH];
        float mx = -1e30f;
        #pragma unroll
        for (int pp = 0; pp < NPATH; pp++) { lg[pp] = sh5[tok][pp] + gb[pp]; mx = fmaxf(mx, lg[pp]); }
        float ssum = 0.f;
        #pragma unroll
        for (int pp = 0; pp < NPATH; pp++) { lg[pp] = expf(lg[pp] - mx); ssum += lg[pp]; }
        float inv = 1.0f / ssum;
        #pragma unroll
        for (int pp = 0; pp < NPATH; pp++) spi[tok][pp] = lg[pp] * inv;
        gmem_out[t0 + tok] = spi[tok][1] + spi[tok][2] + spi[tok][3] + spi[tok][4];
    }
    __syncthreads();

    float4* out4 = (float4*)out;
    #pragma unroll
    for (int lin = tid; lin < GTOK * (DDIM / 4); lin += 256) {
        int tok = lin >> 8, d4 = lin & 255;
        float4 o = make_float4(0.f, 0.f, 0.f, 0.f);
        #pragma unroll
        for (int pp = 0; pp < NPATH; pp++) {
            float4 zp = z4s[tok * Z4PT + pp * 256 + d4];
            float w = spi[tok][pp];
            o.x += w * zp.x; o.y += w * zp.y; o.z += w * zp.z; o.w += w * zp.w;
        }
        out4[(size_t)(t0 + tok) * 256 + d4] = o;
    }
}
#define GATE_SMEM (GTOK * Z4PT * 16)

// ---------------- launch ----------------
extern "C" void kernel_launch(void* const* d_in, const int* in_sizes, int n_in,
                              void* d_out, int out_size) {
    const float* x        = (const float*)d_in[0];
    const float* vt       = (const float*)d_in[1];
    const float* dts      = (const float*)d_in[2];
    const float* r_feat   = (const float*)d_in[3];
    const float* fln_g    = (const float*)d_in[4];
    const float* fln_b    = (const float*)d_in[5];
    const float* w1       = (const float*)d_in[6];
    const float* b1       = (const float*)d_in[7];
    const float* w2       = (const float*)d_in[8];
    const float* b2       = (const float*)d_in[9];
    const float* pg_g     = (const float*)d_in[10];
    const float* pg_b     = (const float*)d_in[11];
    const float* gw       = (const float*)d_in[12];
    const float* gb       = (const float*)d_in[13];

    float* out  = (float*)d_out;                  // [BT, D]
    float* gmem = out + (size_t)BT * DDIM;        // [BT]

    __half* abuf; cudaGetSymbolAddress((void**)&abuf, g_abuf);
    __half* hbuf; cudaGetSymbolAddress((void**)&hbuf, g_hbuf);
    float*  vtp;  cudaGetSymbolAddress((void**)&vtp,  g_vtp);
    __half* w1t;  cudaGetSymbolAddress((void**)&w1t,  g_w1t);
    __half* w2t;  cudaGetSymbolAddress((void**)&w2t,  g_w2t);
    float*  gwt;  cudaGetSymbolAddress((void**)&gwt,  g_gwt);

    cudaFuncSetAttribute(gemm_f16_kernel<0>, cudaFuncAttributeMaxDynamicSharedMemorySize, GEMM_SMEM);
    cudaFuncSetAttribute(gemm_f16_kernel<1>, cudaFuncAttributeMaxDynamicSharedMemorySize, GEMM_SMEM);
    cudaFuncSetAttribute(gate_kernel, cudaFuncAttributeMaxDynamicSharedMemorySize, GATE_SMEM);

    // weight transposes + fp16; gate_w transpose
    {
        dim3 blk(32, 8);
        dim3 g1(HDIM / 32, KF / 32);
        transpose_h_kernel<<<g1, blk>>>(w1, w1t, KF, HDIM);
        dim3 g2(DDIM / 32, HDIM / 32);
        transpose_h_kernel<<<g2, blk>>>(w2, w2t, HDIM, DDIM);
        gwt_kernel<<<(ZD + 255) / 256, 256>>>(gw, gwt);
    }

    // K0: LN(cat(x, r_feat)) -> abuf (fp16)
    ln_fuse_kernel<<<BT, 128>>>(x, r_feat, fln_g, fln_b, abuf);

    // K1: h = fp16(gelu(A @ W1 + b1))  [8192x1152]x[1152x4096]
    {
        dim3 grid(HDIM / 128, BT / 128);
        gemm_f16_kernel<0><<<grid, 256, GEMM_SMEM>>>(abuf, w1t, b1, nullptr, hbuf, BT, HDIM, KF);
    }
    // K2: vt' = h @ W2 + b2 + vt  [8192x4096]x[4096x1024]
    {
        dim3 grid(DDIM / 128, BT / 128);
        gemm_f16_kernel<1><<<grid, 256, GEMM_SMEM>>>(hbuf, w2t, b2, vt, vtp, BT, DDIM, HDIM);
    }
    // K3: gating + mix
    gate_kernel<<<BT / GTOK, 256, GATE_SMEM>>>(vtp, dts, pg_g, pg_b, gwt, gb, out, gmem);
}